// round 1
// baseline (speedup 1.0000x reference)
#include <cuda_runtime.h>
#include <cstdint>

#define TPB    256
#define DDIM   128
#define KCODES 128
#define NPAIR  64

typedef unsigned long long u64;

__device__ __forceinline__ u64 pack2(float lo, float hi) {
    u64 r; asm("mov.b64 %0, {%1, %2};" : "=l"(r) : "f"(lo), "f"(hi)); return r;
}
__device__ __forceinline__ u64 fma2(u64 a, u64 b, u64 c) {
    u64 d; asm("fma.rn.f32x2 %0, %1, %2, %3;" : "=l"(d) : "l"(a), "l"(b), "l"(c)); return d;
}
__device__ __forceinline__ void unpack2(u64 v, float& lo, float& hi) {
    asm("mov.b64 {%0, %1}, %2;" : "=f"(lo), "=f"(hi) : "l"(v));
}

// Shared layout:
//   Wq   : u64[NPAIR][DDIM]  = 65536 B   (Wq[j][d] = packed {W[2j][d], W[2j+1][d]})
//   csh  : float[128]        =   512 B   (0.5 * ||W_k||^2)
//   sidx : int[TPB]          =  1024 B
#define SMEM_BYTES (65536 + 512 + TPB * 4)

__global__ __launch_bounds__(TPB) void vq_kernel(
    const float* __restrict__ z, const float* __restrict__ W,
    float* __restrict__ out, int N)
{
    extern __shared__ unsigned char smem_raw[];
    u64*   Wq   = (u64*)smem_raw;
    float* csh  = (float*)(smem_raw + 65536);
    int*   sidx = (int*)(smem_raw + 65536 + 512);

    const int tid = threadIdx.x;

    // Stage codebook into shared in pair-packed layout (coalesced global reads).
    for (int i = tid; i < KCODES * DDIM; i += TPB) {
        int k = i >> 7, d = i & 127;
        float w = __ldg(W + i);
        ((float*)&Wq[(k >> 1) * DDIM + d])[k & 1] = w;
    }
    // csh[k] = 0.5 * sum_d W[k][d]^2
    if (tid < KCODES) {
        const float4* wr = (const float4*)(W + tid * DDIM);
        float s = 0.f;
        #pragma unroll
        for (int q = 0; q < DDIM / 4; ++q) {
            float4 v = __ldg(wr + q);
            s += v.x * v.x + v.y * v.y + v.z * v.z + v.w * v.w;
        }
        csh[tid] = 0.5f * s;
    }
    __syncthreads();

    const int row = blockIdx.x * TPB + tid;
    const bool valid = row < N;

    // score_k = x . W_k - 0.5*||W_k||^2 ; argmax(score) == argmin(d2).
    u64 acc[NPAIR];
    {
        const float2* c2 = (const float2*)csh;
        #pragma unroll
        for (int j = 0; j < NPAIR; ++j) {
            float2 c = c2[j];
            acc[j] = pack2(-c.x, -c.y);
        }
    }

    const float4* xrow = (const float4*)(z + (size_t)row * DDIM);
    #pragma unroll 1
    for (int d4 = 0; d4 < DDIM / 4; ++d4) {
        float4 xv = valid ? __ldg(xrow + d4) : make_float4(0.f, 0.f, 0.f, 0.f);
        u64 X0 = pack2(xv.x, xv.x);
        u64 X1 = pack2(xv.y, xv.y);
        u64 X2 = pack2(xv.z, xv.z);
        u64 X3 = pack2(xv.w, xv.w);
        // base points at Wq[j=0][d = 4*d4], viewed as 16B vectors
        const ulonglong2* wp = (const ulonglong2*)(Wq + d4 * 4);
        #pragma unroll
        for (int j = 0; j < NPAIR; ++j) {
            ulonglong2 wa = wp[j * 64];       // packed pairs for d = 4*d4, 4*d4+1
            ulonglong2 wb = wp[j * 64 + 1];   // packed pairs for d = 4*d4+2, 4*d4+3
            acc[j] = fma2(X0, wa.x, acc[j]);
            acc[j] = fma2(X1, wa.y, acc[j]);
            acc[j] = fma2(X2, wb.x, acc[j]);
            acc[j] = fma2(X3, wb.y, acc[j]);
        }
    }

    // Argmax with first-index tiebreak (== jnp.argmin first-min on d2).
    float best = -3.402823466e38f;
    int bidx = 0;
    #pragma unroll
    for (int j = 0; j < NPAIR; ++j) {
        float s0, s1; unpack2(acc[j], s0, s1);
        if (s0 > best) { best = s0; bidx = 2 * j; }
        if (s1 > best) { best = s1; bidx = 2 * j + 1; }
    }
    sidx[tid] = bidx;
    __syncthreads();

    // Cooperative, fully-coalesced gather of W[idx] into BOTH output halves.
    const int base = blockIdx.x * TPB;
    const int rows = min(TPB, N - base);
    float4* o1 = (float4*)out;
    float4* o2 = o1 + (size_t)N * (DDIM / 4);
    for (int i = tid; i < rows * (DDIM / 4); i += TPB) {
        int r = i >> 5, d4i = i & 31;
        const float4* wsrc = (const float4*)(W + sidx[r] * DDIM);
        float4 v = __ldg(wsrc + d4i);
        size_t off = (size_t)(base + r) * (DDIM / 4) + d4i;
        o1[off] = v;
        o2[off] = v;
    }
}

extern "C" void kernel_launch(void* const* d_in, const int* in_sizes, int n_in,
                              void* d_out, int out_size) {
    const float* z = (const float*)d_in[0];
    const float* W = (const float*)d_in[1];
    int N = in_sizes[0] / DDIM;

    cudaFuncSetAttribute(vq_kernel, cudaFuncAttributeMaxDynamicSharedMemorySize, SMEM_BYTES);
    int grid = (N + TPB - 1) / TPB;
    vq_kernel<<<grid, TPB, SMEM_BYTES>>>(z, W, (float*)d_out, N);
}

// round 2
// speedup vs baseline: 1.3296x; 1.3296x over previous
#include <cuda_runtime.h>
#include <cstdint>

#define TPB    128
#define MROWS  4
#define RPC    (TPB * MROWS)      // 512 rows per CTA
#define DDIM   128
#define KCODES 128
#define KT     32                 // codes per K-tile
#define NKT    (KCODES / KT)      // 4
#define PAIRS  (KT / 2)           // 16

typedef unsigned long long u64;

__device__ __forceinline__ u64 pack2(float lo, float hi) {
    u64 r; asm("mov.b64 %0, {%1, %2};" : "=l"(r) : "f"(lo), "f"(hi)); return r;
}
__device__ __forceinline__ u64 fma2(u64 a, u64 b, u64 c) {
    u64 d; asm("fma.rn.f32x2 %0, %1, %2, %3;" : "=l"(d) : "l"(a), "l"(b), "l"(c)); return d;
}
__device__ __forceinline__ void unpack2(u64 v, float& lo, float& hi) {
    asm("mov.b64 {%0, %1}, %2;" : "=f"(lo), "=f"(hi) : "l"(v));
}

// Shared: Wq u64[64][128] = 65536 B (Wq[j][d] = {W[2j][d], W[2j+1][d]}),
//         csh float[128]  = 512 B   (0.5*||W_k||^2),
//         sidx int[RPC]   = 2048 B
#define SMEM_BYTES (65536 + 512 + RPC * 4)

__global__ __launch_bounds__(TPB, 2) void vq_kernel(
    const float* __restrict__ z, const float* __restrict__ W,
    float* __restrict__ out, int N)
{
    extern __shared__ unsigned char smem_raw[];
    u64*   Wq   = (u64*)smem_raw;
    float* csh  = (float*)(smem_raw + 65536);
    int*   sidx = (int*)(smem_raw + 65536 + 512);

    const int tid = threadIdx.x;

    // Stage codebook into shared, pair-packed (coalesced global reads).
    for (int i = tid; i < KCODES * DDIM; i += TPB) {
        int k = i >> 7, d = i & 127;
        ((float*)&Wq[(k >> 1) * DDIM + d])[k & 1] = __ldg(W + i);
    }
    if (tid < KCODES) {
        const float4* wr = (const float4*)(W + tid * DDIM);
        float s = 0.f;
        #pragma unroll
        for (int q = 0; q < DDIM / 4; ++q) {
            float4 v = __ldg(wr + q);
            s += v.x * v.x + v.y * v.y + v.z * v.z + v.w * v.w;
        }
        csh[tid] = 0.5f * s;
    }
    __syncthreads();

    const int base = blockIdx.x * RPC;
    size_t rowoff[MROWS];
    bool   valid[MROWS];
    #pragma unroll
    for (int m = 0; m < MROWS; ++m) {
        int r = base + m * TPB + tid;        // lanes -> consecutive rows
        valid[m]  = r < N;
        rowoff[m] = (size_t)r * DDIM;
    }

    float best[MROWS];
    int   bidx[MROWS];
    #pragma unroll
    for (int m = 0; m < MROWS; ++m) { best[m] = -3.402823466e38f; bidx[m] = 0; }

    #pragma unroll 1
    for (int kt = 0; kt < NKT; ++kt) {
        // acc[j][m] = score of code (kt*KT + 2j, 2j+1) for row m
        u64 acc[PAIRS][MROWS];
        #pragma unroll
        for (int j = 0; j < PAIRS; ++j) {
            int c0 = kt * KT + 2 * j;
            u64 ini = pack2(-csh[c0], -csh[c0 + 1]);
            #pragma unroll
            for (int m = 0; m < MROWS; ++m) acc[j][m] = ini;
        }

        const u64* Wk = Wq + (kt * PAIRS) * DDIM;

        #pragma unroll 1
        for (int d8 = 0; d8 < DDIM / 8; ++d8) {
            // 32B (full sector) of x per row per iteration
            u64 X[MROWS][8];
            #pragma unroll
            for (int m = 0; m < MROWS; ++m) {
                const float4* xp = (const float4*)(z + rowoff[m]) + 2 * d8;
                float4 a = valid[m] ? __ldg(xp)     : make_float4(0.f, 0.f, 0.f, 0.f);
                float4 b = valid[m] ? __ldg(xp + 1) : make_float4(0.f, 0.f, 0.f, 0.f);
                X[m][0] = pack2(a.x, a.x); X[m][1] = pack2(a.y, a.y);
                X[m][2] = pack2(a.z, a.z); X[m][3] = pack2(a.w, a.w);
                X[m][4] = pack2(b.x, b.x); X[m][5] = pack2(b.y, b.y);
                X[m][6] = pack2(b.z, b.z); X[m][7] = pack2(b.w, b.w);
            }
            #pragma unroll
            for (int j = 0; j < PAIRS; ++j) {
                const ulonglong2* wp = (const ulonglong2*)(Wk + j * DDIM + d8 * 8);
                #pragma unroll
                for (int h = 0; h < 4; ++h) {
                    ulonglong2 w = wp[h];          // code-pair j at d = d8*8+2h, +1
                    #pragma unroll
                    for (int m = 0; m < MROWS; ++m) {
                        acc[j][m] = fma2(X[m][2 * h],     w.x, acc[j][m]);
                        acc[j][m] = fma2(X[m][2 * h + 1], w.y, acc[j][m]);
                    }
                }
            }
        }

        // Fold this K-tile into the running argmax (strict >, ascending index
        // order == first-index tiebreak of jnp.argmin on d2).
        #pragma unroll
        for (int j = 0; j < PAIRS; ++j) {
            int c0 = kt * KT + 2 * j;
            #pragma unroll
            for (int m = 0; m < MROWS; ++m) {
                float s0, s1; unpack2(acc[j][m], s0, s1);
                if (s0 > best[m]) { best[m] = s0; bidx[m] = c0; }
                if (s1 > best[m]) { best[m] = s1; bidx[m] = c0 + 1; }
            }
        }
    }

    #pragma unroll
    for (int m = 0; m < MROWS; ++m) sidx[m * TPB + tid] = bidx[m];
    __syncthreads();

    // Cooperative, fully-coalesced gather of W[idx] into BOTH output halves.
    const int rows = min(RPC, N - base);
    float4* o1 = (float4*)out;
    float4* o2 = o1 + (size_t)N * (DDIM / 4);
    for (int i = tid; i < rows * (DDIM / 4); i += TPB) {
        int r = i >> 5, dq = i & 31;
        float4 v = __ldg((const float4*)(W + sidx[r] * DDIM) + dq);
        size_t off = (size_t)(base + r) * (DDIM / 4) + dq;
        o1[off] = v;
        o2[off] = v;
    }
}

extern "C" void kernel_launch(void* const* d_in, const int* in_sizes, int n_in,
                              void* d_out, int out_size) {
    const float* z = (const float*)d_in[0];
    const float* W = (const float*)d_in[1];
    int N = in_sizes[0] / DDIM;

    cudaFuncSetAttribute(vq_kernel, cudaFuncAttributeMaxDynamicSharedMemorySize, SMEM_BYTES);
    int grid = (N + RPC - 1) / RPC;
    vq_kernel<<<grid, TPB, SMEM_BYTES>>>(z, W, (float*)d_out, N);
}

// round 6
// speedup vs baseline: 2.1072x; 1.5849x over previous
#include <cuda_runtime.h>
#include <cuda_bf16.h>
#include <cstdint>

#define TPB     128
#define TILE_M  128
#define DDIM    128
#define KCODES  128
#define MARGIN  0.01f

// ---- shared layout (bytes) ----
#define Z_OFF(b)   ((b) * 65536)            // fp32 z tile: 128 rows * 512B, x2 buffers
#define WP_OFF(p)  (131072 + (p) * 32768)   // bf16 W plane: 128 rows * 256B, hi/lo
#define CSH_OFF    196608                   // 128 floats
#define SIDX_OFF   197120                   // 128 ints
#define SMEM_BYTES 197632

// swizzled addressing (conflict-free for the mma fragment patterns)
__device__ __forceinline__ uint32_t a_off(int m, int w64) {      // fp32 pairs, 8B units
    return (uint32_t)(m * 512 + ((w64 ^ ((m & 7) * 4)) * 8));
}
__device__ __forceinline__ uint32_t w_off(int n, int w32) {      // bf16 pairs, 4B units
    return (uint32_t)(n * 256 + ((w32 ^ ((n & 7) * 4)) * 4));
}

__device__ __forceinline__ uint32_t smem_u32(const void* p) {
    uint32_t a;
    asm("{ .reg .u64 t; cvta.to.shared.u64 t, %1; cvt.u32.u64 %0, t; }" : "=r"(a) : "l"(p));
    return a;
}
// pack {low=x0, high=x1} as bf16x2
__device__ __forceinline__ uint32_t pack_bf16x2(float x0, float x1) {
    uint32_t r;
    asm("cvt.rn.bf16x2.f32 %0, %1, %2;" : "=r"(r) : "f"(x1), "f"(x0));
    return r;
}
__device__ __forceinline__ void split_pair(float x0, float x1, uint32_t& hi, uint32_t& lo) {
    hi = pack_bf16x2(x0, x1);
    float h0 = __uint_as_float(hi << 16);
    float h1 = __uint_as_float(hi & 0xffff0000u);
    lo = pack_bf16x2(x0 - h0, x1 - h1);
}
__device__ __forceinline__ void cp_async16(uint32_t dst, const void* src) {
    asm volatile("cp.async.cg.shared.global [%0], [%1], 16;" :: "r"(dst), "l"(src) : "memory");
}
#define CP_COMMIT() asm volatile("cp.async.commit_group;" ::: "memory")
#define CP_WAIT0()  asm volatile("cp.async.wait_group 0;" ::: "memory")

__device__ __forceinline__ void mma_bf16(float* d, const uint32_t* a, uint32_t b0, uint32_t b1) {
    asm volatile("mma.sync.aligned.m16n8k16.row.col.f32.bf16.bf16.f32 "
                 "{%0,%1,%2,%3}, {%4,%5,%6,%7}, {%8,%9}, {%0,%1,%2,%3};"
                 : "+f"(d[0]), "+f"(d[1]), "+f"(d[2]), "+f"(d[3])
                 : "r"(a[0]), "r"(a[1]), "r"(a[2]), "r"(a[3]), "r"(b0), "r"(b1));
}

__device__ __forceinline__ bool better(float v, int i, float v2, int i2) {
    return (v > v2) || (v == v2 && i < i2);
}

__device__ __forceinline__ void load_tile(const float* __restrict__ z, int t, int N,
                                          uint32_t sb, int buf, int tid) {
    const size_t rowbase = (size_t)t * TILE_M;
    #pragma unroll 4
    for (int i = tid; i < TILE_M * 32; i += TPB) {
        int m = i >> 5, ch = i & 31;
        if (rowbase + m < (size_t)N) {
            uint32_t dst = sb + Z_OFF(buf) + (uint32_t)(m * 512 + (((2 * ch) ^ ((m & 7) * 4)) * 8));
            cp_async16(dst, z + (rowbase + m) * DDIM + ch * 4);
        }
    }
}

__device__ float exact_sm(const char* zb, int rloc, const float* __restrict__ W, int k) {
    const float* wr = W + (size_t)k * DDIM;
    float s = 0.f;
    #pragma unroll 8
    for (int w = 0; w < 64; ++w) {
        float2 p = *(const float2*)(zb + a_off(rloc, w));
        s += p.x * __ldg(wr + 2 * w) + p.y * __ldg(wr + 2 * w + 1);
    }
    return s;
}

__global__ __launch_bounds__(TPB, 1) void vq_hmma_kernel(
    const float* __restrict__ z, const float* __restrict__ W,
    float* __restrict__ out, int N, int ntiles)
{
    extern __shared__ char smem[];
    const uint32_t sb = smem_u32(smem);
    const int tid  = threadIdx.x;
    const int wid  = tid >> 5, lane = tid & 31;
    const int g    = lane >> 2, c = lane & 3;

    float* csh  = (float*)(smem + CSH_OFF);
    int*   sidx = (int*)(smem + SIDX_OFF);

    // ---- stage W split planes + csh (once) ----
    for (int i = tid; i < KCODES * 64; i += TPB) {
        int n = i >> 6, w = i & 63;
        float x0 = __ldg(W + n * DDIM + 2 * w);
        float x1 = __ldg(W + n * DDIM + 2 * w + 1);
        uint32_t hi, lo; split_pair(x0, x1, hi, lo);
        *(uint32_t*)(smem + WP_OFF(0) + w_off(n, w)) = hi;
        *(uint32_t*)(smem + WP_OFF(1) + w_off(n, w)) = lo;
    }
    {
        const float4* wr = (const float4*)(W + (size_t)tid * DDIM);
        float s = 0.f;
        #pragma unroll
        for (int q = 0; q < DDIM / 4; ++q) {
            float4 v = __ldg(wr + q);
            s += v.x * v.x + v.y * v.y + v.z * v.z + v.w * v.w;
        }
        csh[tid] = 0.5f * s;
    }
    __syncthreads();

    const int nct = gridDim.x;
    int t = blockIdx.x;
    int buf = 0;

    load_tile(z, t, N, sb, 0, tid);
    CP_COMMIT(); CP_WAIT0();
    __syncthreads();

    while (true) {
        const int tn = t + nct;
        const bool hn = tn < ntiles;
        if (hn) { load_tile(z, tn, N, sb, buf ^ 1, tid); CP_COMMIT(); }

        // ---- compute: scores[wid*32+r][k] via 2-way bf16 split mma ----
        float acc[2][16][4];
        #pragma unroll
        for (int mt = 0; mt < 2; ++mt)
            #pragma unroll
            for (int nt = 0; nt < 16; ++nt)
                #pragma unroll
                for (int q = 0; q < 4; ++q) acc[mt][nt][q] = 0.f;

        const char* zb  = smem + Z_OFF(buf);
        const char* wp0 = smem + WP_OFF(0);
        const char* wp1 = smem + WP_OFF(1);

        #pragma unroll 1
        for (int kt = 0; kt < 8; ++kt) {
            uint32_t Ah[2][4], Al[2][4];
            #pragma unroll
            for (int mt = 0; mt < 2; ++mt) {
                int r0 = wid * 32 + mt * 16 + g;
                float2 p0 = *(const float2*)(zb + a_off(r0,     8 * kt + c));
                float2 p1 = *(const float2*)(zb + a_off(r0 + 8, 8 * kt + c));
                float2 p2 = *(const float2*)(zb + a_off(r0,     8 * kt + c + 4));
                float2 p3 = *(const float2*)(zb + a_off(r0 + 8, 8 * kt + c + 4));
                split_pair(p0.x, p0.y, Ah[mt][0], Al[mt][0]);
                split_pair(p1.x, p1.y, Ah[mt][1], Al[mt][1]);
                split_pair(p2.x, p2.y, Ah[mt][2], Al[mt][2]);
                split_pair(p3.x, p3.y, Ah[mt][3], Al[mt][3]);
            }
            #pragma unroll
            for (int nt = 0; nt < 16; ++nt) {
                int n = 8 * nt + g;
                uint32_t bh0 = *(const uint32_t*)(wp0 + w_off(n, 8 * kt + c));
                uint32_t bh1 = *(const uint32_t*)(wp0 + w_off(n, 8 * kt + c + 4));
                uint32_t bl0 = *(const uint32_t*)(wp1 + w_off(n, 8 * kt + c));
                uint32_t bl1 = *(const uint32_t*)(wp1 + w_off(n, 8 * kt + c + 4));
                #pragma unroll
                for (int mt = 0; mt < 2; ++mt) {
                    mma_bf16(acc[mt][nt], Ah[mt], bh0, bh1);
                    mma_bf16(acc[mt][nt], Ah[mt], bl0, bl1);
                    mma_bf16(acc[mt][nt], Al[mt], bh0, bh1);
                }
            }
        }

        // ---- epilogue: top-2 argmax per row, merge across the 4-lane group ----
        #pragma unroll
        for (int mt = 0; mt < 2; ++mt) {
            #pragma unroll
            for (int rh = 0; rh < 2; ++rh) {
                float v1 = -3.402823466e38f, v2 = -3.402823466e38f;
                int i1 = 0, i2 = 0;
                #pragma unroll
                for (int nt = 0; nt < 16; ++nt) {
                    int k0 = nt * 8 + c * 2;
                    float s0 = acc[mt][nt][rh * 2]     - csh[k0];
                    float s1 = acc[mt][nt][rh * 2 + 1] - csh[k0 + 1];
                    if (s0 > v1)      { v2 = v1; i2 = i1; v1 = s0; i1 = k0; }
                    else if (s0 > v2) { v2 = s0; i2 = k0; }
                    if (s1 > v1)      { v2 = v1; i2 = i1; v1 = s1; i1 = k0 + 1; }
                    else if (s1 > v2) { v2 = s1; i2 = k0 + 1; }
                }
                #pragma unroll
                for (int m_ = 1; m_ <= 2; m_ <<= 1) {
                    float ov1 = __shfl_xor_sync(0xffffffffu, v1, m_);
                    int   oi1 = __shfl_xor_sync(0xffffffffu, i1, m_);
                    float ov2 = __shfl_xor_sync(0xffffffffu, v2, m_);
                    int   oi2 = __shfl_xor_sync(0xffffffffu, i2, m_);
                    if (better(ov1, oi1, v1, i1)) {
                        if (better(v1, i1, ov2, oi2)) { v2 = v1; i2 = i1; }
                        else                          { v2 = ov2; i2 = oi2; }
                        v1 = ov1; i1 = oi1;
                    } else if (better(ov1, oi1, v2, i2)) {
                        v2 = ov1; i2 = oi1;
                    }
                }
                if (c == 0) {
                    int rloc = wid * 32 + mt * 16 + rh * 8 + g;
                    int rg   = t * TILE_M + rloc;
                    int choice = i1;
                    if (rg < N && (v1 - v2) < MARGIN) {
                        float e1 = exact_sm(zb, rloc, W, i1) - csh[i1];
                        float e2 = exact_sm(zb, rloc, W, i2) - csh[i2];
                        if (better(e2, i2, e1, i1)) choice = i2;
                    }
                    sidx[rloc] = choice;
                }
            }
        }
        __syncthreads();

        // ---- gather W[idx] and write both output halves (coalesced) ----
        {
            const int base = t * TILE_M;
            const int rows = min(TILE_M, N - base);
            float4* o1 = (float4*)out;
            float4* o2 = o1 + (size_t)N * (DDIM / 4);
            for (int i = tid; i < rows * (DDIM / 4); i += TPB) {
                int r = i >> 5, dq = i & 31;
                float4 v = __ldg((const float4*)(W + (size_t)sidx[r] * DDIM) + dq);
                size_t off = (size_t)(base + r) * (DDIM / 4) + dq;
                o1[off] = v;
                o2[off] = v;
            }
        }

        if (!hn) break;
        CP_WAIT0();
        __syncthreads();
        t = tn; buf ^= 1;
    }
}

extern "C" void kernel_launch(void* const* d_in, const int* in_sizes, int n_in,
                              void* d_out, int out_size) {
    const float* z = (const float*)d_in[0];
    const float* W = (const float*)d_in[1];
    int N = in_sizes[0] / DDIM;
    int ntiles = (N + TILE_M - 1) / TILE_M;

    int nsm = 148;
    cudaDeviceGetAttribute(&nsm, cudaDevAttrMultiProcessorCount, 0);

    cudaFuncSetAttribute(vq_hmma_kernel, cudaFuncAttributeMaxDynamicSharedMemorySize, SMEM_BYTES);
    int grid = ntiles < nsm ? ntiles : nsm;
    vq_hmma_kernel<<<grid, TPB, SMEM_BYTES>>>(z, W, (float*)d_out, N, ntiles);
}

// round 7
// speedup vs baseline: 2.1195x; 1.0058x over previous
#include <cuda_runtime.h>
#include <cuda_bf16.h>
#include <cstdint>

#define TPB     128
#define TILE_M  128
#define DDIM    128
#define KCODES  128
#define MARGIN  0.01f

// ---- shared layout (bytes) ----
#define Z_OFF(b)   ((b) * 65536)            // fp32 z tile: 128 rows * 512B, x2 buffers
#define WP_OFF(p)  (131072 + (p) * 32768)   // bf16 W plane: 128 rows * 256B, hi/lo
#define CSH_OFF    196608                   // 128 floats
#define SIDX_OFF   197120                   // 128 ints
#define SMEM_BYTES 197632

// swizzled addressing (conflict-free for the mma fragment patterns)
__device__ __forceinline__ uint32_t a_off(int m, int w64) {      // fp32 pairs, 8B units
    return (uint32_t)(m * 512 + ((w64 ^ ((m & 7) * 4)) * 8));
}
__device__ __forceinline__ uint32_t w_off(int n, int w32) {      // bf16 pairs, 4B units
    return (uint32_t)(n * 256 + ((w32 ^ ((n & 7) * 4)) * 4));
}

__device__ __forceinline__ uint32_t smem_u32(const void* p) {
    uint32_t a;
    asm("{ .reg .u64 t; cvta.to.shared.u64 t, %1; cvt.u32.u64 %0, t; }" : "=r"(a) : "l"(p));
    return a;
}
// pack {low=x0, high=x1} as bf16x2
__device__ __forceinline__ uint32_t pack_bf16x2(float x0, float x1) {
    uint32_t r;
    asm("cvt.rn.bf16x2.f32 %0, %1, %2;" : "=r"(r) : "f"(x1), "f"(x0));
    return r;
}
__device__ __forceinline__ void split_pair(float x0, float x1, uint32_t& hi, uint32_t& lo) {
    hi = pack_bf16x2(x0, x1);
    float h0 = __uint_as_float(hi << 16);
    float h1 = __uint_as_float(hi & 0xffff0000u);
    lo = pack_bf16x2(x0 - h0, x1 - h1);
}
__device__ __forceinline__ void cp_async16(uint32_t dst, const void* src) {
    asm volatile("cp.async.cg.shared.global [%0], [%1], 16;" :: "r"(dst), "l"(src) : "memory");
}
#define CP_COMMIT() asm volatile("cp.async.commit_group;" ::: "memory")
#define CP_WAIT0()  asm volatile("cp.async.wait_group 0;" ::: "memory")

__device__ __forceinline__ void mma_bf16(float* d, const uint32_t* a, uint32_t b0, uint32_t b1) {
    asm volatile("mma.sync.aligned.m16n8k16.row.col.f32.bf16.bf16.f32 "
                 "{%0,%1,%2,%3}, {%4,%5,%6,%7}, {%8,%9}, {%0,%1,%2,%3};"
                 : "+f"(d[0]), "+f"(d[1]), "+f"(d[2]), "+f"(d[3])
                 : "r"(a[0]), "r"(a[1]), "r"(a[2]), "r"(a[3]), "r"(b0), "r"(b1));
}

__device__ __forceinline__ bool better(float v, int i, float v2, int i2) {
    return (v > v2) || (v == v2 && i < i2);
}

__device__ __forceinline__ void load_tile(const float* __restrict__ z, int t, int N,
                                          uint32_t sb, int buf, int tid) {
    const size_t rowbase = (size_t)t * TILE_M;
    #pragma unroll 4
    for (int i = tid; i < TILE_M * 32; i += TPB) {
        int m = i >> 5, ch = i & 31;
        if (rowbase + m < (size_t)N) {
            uint32_t dst = sb + Z_OFF(buf) + (uint32_t)(m * 512 + (((2 * ch) ^ ((m & 7) * 4)) * 8));
            cp_async16(dst, z + (rowbase + m) * DDIM + ch * 4);
        }
    }
}

__device__ float exact_sm(const char* zb, int rloc, const float* __restrict__ W, int k) {
    const float* wr = W + (size_t)k * DDIM;
    float s = 0.f;
    #pragma unroll 8
    for (int w = 0; w < 64; ++w) {
        float2 p = *(const float2*)(zb + a_off(rloc, w));
        s += p.x * __ldg(wr + 2 * w) + p.y * __ldg(wr + 2 * w + 1);
    }
    return s;
}

__global__ __launch_bounds__(TPB, 1) void vq_hmma_kernel(
    const float* __restrict__ z, const float* __restrict__ W,
    float* __restrict__ out, int N, int ntiles)
{
    extern __shared__ char smem[];
    const uint32_t sb = smem_u32(smem);
    const int tid  = threadIdx.x;
    const int wid  = tid >> 5, lane = tid & 31;
    const int g    = lane >> 2, c = lane & 3;

    float* csh  = (float*)(smem + CSH_OFF);
    int*   sidx = (int*)(smem + SIDX_OFF);

    // ---- stage W split planes + csh (once) ----
    for (int i = tid; i < KCODES * 64; i += TPB) {
        int n = i >> 6, w = i & 63;
        float x0 = __ldg(W + n * DDIM + 2 * w);
        float x1 = __ldg(W + n * DDIM + 2 * w + 1);
        uint32_t hi, lo; split_pair(x0, x1, hi, lo);
        *(uint32_t*)(smem + WP_OFF(0) + w_off(n, w)) = hi;
        *(uint32_t*)(smem + WP_OFF(1) + w_off(n, w)) = lo;
    }
    {
        const float4* wr = (const float4*)(W + (size_t)tid * DDIM);
        float s = 0.f;
        #pragma unroll
        for (int q = 0; q < DDIM / 4; ++q) {
            float4 v = __ldg(wr + q);
            s += v.x * v.x + v.y * v.y + v.z * v.z + v.w * v.w;
        }
        csh[tid] = 0.5f * s;
    }
    __syncthreads();

    const int nct = gridDim.x;
    int t = blockIdx.x;
    int buf = 0;

    load_tile(z, t, N, sb, 0, tid);
    CP_COMMIT(); CP_WAIT0();
    __syncthreads();

    while (true) {
        const int tn = t + nct;
        const bool hn = tn < ntiles;
        if (hn) { load_tile(z, tn, N, sb, buf ^ 1, tid); CP_COMMIT(); }

        // ---- compute: scores[wid*32+r][k] via 2-way bf16 split mma ----
        float acc[2][16][4];
        #pragma unroll
        for (int mt = 0; mt < 2; ++mt)
            #pragma unroll
            for (int nt = 0; nt < 16; ++nt)
                #pragma unroll
                for (int q = 0; q < 4; ++q) acc[mt][nt][q] = 0.f;

        const char* zb  = smem + Z_OFF(buf);
        const char* wp0 = smem + WP_OFF(0);
        const char* wp1 = smem + WP_OFF(1);

        #pragma unroll 1
        for (int kt = 0; kt < 8; ++kt) {
            uint32_t Ah[2][4], Al[2][4];
            #pragma unroll
            for (int mt = 0; mt < 2; ++mt) {
                int r0 = wid * 32 + mt * 16 + g;
                float2 p0 = *(const float2*)(zb + a_off(r0,     8 * kt + c));
                float2 p1 = *(const float2*)(zb + a_off(r0 + 8, 8 * kt + c));
                float2 p2 = *(const float2*)(zb + a_off(r0,     8 * kt + c + 4));
                float2 p3 = *(const float2*)(zb + a_off(r0 + 8, 8 * kt + c + 4));
                split_pair(p0.x, p0.y, Ah[mt][0], Al[mt][0]);
                split_pair(p1.x, p1.y, Ah[mt][1], Al[mt][1]);
                split_pair(p2.x, p2.y, Ah[mt][2], Al[mt][2]);
                split_pair(p3.x, p3.y, Ah[mt][3], Al[mt][3]);
            }
            #pragma unroll
            for (int nt = 0; nt < 16; ++nt) {
                int n = 8 * nt + g;
                uint32_t bh0 = *(const uint32_t*)(wp0 + w_off(n, 8 * kt + c));
                uint32_t bh1 = *(const uint32_t*)(wp0 + w_off(n, 8 * kt + c + 4));
                uint32_t bl0 = *(const uint32_t*)(wp1 + w_off(n, 8 * kt + c));
                uint32_t bl1 = *(const uint32_t*)(wp1 + w_off(n, 8 * kt + c + 4));
                #pragma unroll
                for (int mt = 0; mt < 2; ++mt) {
                    mma_bf16(acc[mt][nt], Ah[mt], bh0, bh1);
                    mma_bf16(acc[mt][nt], Ah[mt], bl0, bl1);
                    mma_bf16(acc[mt][nt], Al[mt], bh0, bh1);
                }
            }
        }

        // ---- epilogue: top-2 argmax per row, merge across the 4-lane group ----
        #pragma unroll
        for (int mt = 0; mt < 2; ++mt) {
            #pragma unroll
            for (int rh = 0; rh < 2; ++rh) {
                float v1 = -3.402823466e38f, v2 = -3.402823466e38f;
                int i1 = 0, i2 = 0;
                #pragma unroll
                for (int nt = 0; nt < 16; ++nt) {
                    int k0 = nt * 8 + c * 2;
                    float s0 = acc[mt][nt][rh * 2]     - csh[k0];
                    float s1 = acc[mt][nt][rh * 2 + 1] - csh[k0 + 1];
                    if (s0 > v1)      { v2 = v1; i2 = i1; v1 = s0; i1 = k0; }
                    else if (s0 > v2) { v2 = s0; i2 = k0; }
                    if (s1 > v1)      { v2 = v1; i2 = i1; v1 = s1; i1 = k0 + 1; }
                    else if (s1 > v2) { v2 = s1; i2 = k0 + 1; }
                }
                #pragma unroll
                for (int m_ = 1; m_ <= 2; m_ <<= 1) {
                    float ov1 = __shfl_xor_sync(0xffffffffu, v1, m_);
                    int   oi1 = __shfl_xor_sync(0xffffffffu, i1, m_);
                    float ov2 = __shfl_xor_sync(0xffffffffu, v2, m_);
                    int   oi2 = __shfl_xor_sync(0xffffffffu, i2, m_);
                    if (better(ov1, oi1, v1, i1)) {
                        if (better(v1, i1, ov2, oi2)) { v2 = v1; i2 = i1; }
                        else                          { v2 = ov2; i2 = oi2; }
                        v1 = ov1; i1 = oi1;
                    } else if (better(ov1, oi1, v2, i2)) {
                        v2 = ov1; i2 = oi1;
                    }
                }
                if (c == 0) {
                    int rloc = wid * 32 + mt * 16 + rh * 8 + g;
                    int rg   = t * TILE_M + rloc;
                    int choice = i1;
                    if (rg < N && (v1 - v2) < MARGIN) {
                        float e1 = exact_sm(zb, rloc, W, i1) - csh[i1];
                        float e2 = exact_sm(zb, rloc, W, i2) - csh[i2];
                        if (better(e2, i2, e1, i1)) choice = i2;
                    }
                    sidx[rloc] = choice;
                }
            }
        }
        __syncthreads();

        // ---- gather W[idx] and write both output halves (coalesced) ----
        {
            const int base = t * TILE_M;
            const int rows = min(TILE_M, N - base);
            float4* o1 = (float4*)out;
            float4* o2 = o1 + (size_t)N * (DDIM / 4);
            for (int i = tid; i < rows * (DDIM / 4); i += TPB) {
                int r = i >> 5, dq = i & 31;
                float4 v = __ldg((const float4*)(W + (size_t)sidx[r] * DDIM) + dq);
                size_t off = (size_t)(base + r) * (DDIM / 4) + dq;
                o1[off] = v;
                o2[off] = v;
            }
        }

        if (!hn) break;
        CP_WAIT0();
        __syncthreads();
        t = tn; buf ^= 1;
    }
}

extern "C" void kernel_launch(void* const* d_in, const int* in_sizes, int n_in,
                              void* d_out, int out_size) {
    const float* z = (const float*)d_in[0];
    const float* W = (const float*)d_in[1];
    int N = in_sizes[0] / DDIM;
    int ntiles = (N + TILE_M - 1) / TILE_M;

    int nsm = 148;
    cudaDeviceGetAttribute(&nsm, cudaDevAttrMultiProcessorCount, 0);

    cudaFuncSetAttribute(vq_hmma_kernel, cudaFuncAttributeMaxDynamicSharedMemorySize, SMEM_BYTES);
    int grid = ntiles < nsm ? ntiles : nsm;
    vq_hmma_kernel<<<grid, TPB, SMEM_BYTES>>>(z, W, (float*)d_out, N, ntiles);
}

// round 8
// speedup vs baseline: 2.5899x; 1.2220x over previous
#include <cuda_runtime.h>
#include <cuda_bf16.h>
#include <cstdint>

#define TPB     256
#define TILE_M  128
#define DDIM    128
#define KCODES  128
#define MARGIN  0.01f

// ---- shared layout (bytes) ----
#define Z_OFF(b)   ((b) * 65536)            // fp32 z tile: 128 rows * 512B, x2 buffers
#define WP_OFF(p)  (131072 + (p) * 32768)   // bf16 W plane: 128 rows * 256B, hi/lo
#define CSH_OFF    196608                   // 128 floats
#define SIDX_OFF   197120                   // 128 ints
#define SMEM_BYTES 197632

// swizzled addressing (conflict-free for the mma fragment patterns)
__device__ __forceinline__ uint32_t a_off(int m, int w64) {      // fp32 pairs, 8B units
    return (uint32_t)(m * 512 + ((w64 ^ ((m & 7) * 4)) * 8));
}
__device__ __forceinline__ uint32_t w_off(int n, int w32) {      // bf16 pairs, 4B units
    return (uint32_t)(n * 256 + ((w32 ^ ((n & 7) * 4)) * 4));
}

__device__ __forceinline__ uint32_t smem_u32(const void* p) {
    uint32_t a;
    asm("{ .reg .u64 t; cvta.to.shared.u64 t, %1; cvt.u32.u64 %0, t; }" : "=r"(a) : "l"(p));
    return a;
}
// pack {low=x0, high=x1} as bf16x2
__device__ __forceinline__ uint32_t pack_bf16x2(float x0, float x1) {
    uint32_t r;
    asm("cvt.rn.bf16x2.f32 %0, %1, %2;" : "=r"(r) : "f"(x1), "f"(x0));
    return r;
}
__device__ __forceinline__ void split_pair(float x0, float x1, uint32_t& hi, uint32_t& lo) {
    hi = pack_bf16x2(x0, x1);
    float h0 = __uint_as_float(hi << 16);
    float h1 = __uint_as_float(hi & 0xffff0000u);
    lo = pack_bf16x2(x0 - h0, x1 - h1);
}
__device__ __forceinline__ void cp_async16(uint32_t dst, const void* src) {
    asm volatile("cp.async.cg.shared.global [%0], [%1], 16;" :: "r"(dst), "l"(src) : "memory");
}
#define CP_COMMIT() asm volatile("cp.async.commit_group;" ::: "memory")
#define CP_WAIT0()  asm volatile("cp.async.wait_group 0;" ::: "memory")

__device__ __forceinline__ void mma_bf16(float* d, const uint32_t* a, uint32_t b0, uint32_t b1) {
    asm volatile("mma.sync.aligned.m16n8k16.row.col.f32.bf16.bf16.f32 "
                 "{%0,%1,%2,%3}, {%4,%5,%6,%7}, {%8,%9}, {%0,%1,%2,%3};"
                 : "+f"(d[0]), "+f"(d[1]), "+f"(d[2]), "+f"(d[3])
                 : "r"(a[0]), "r"(a[1]), "r"(a[2]), "r"(a[3]), "r"(b0), "r"(b1));
}

__device__ __forceinline__ bool better(float v, int i, float v2, int i2) {
    return (v > v2) || (v == v2 && i < i2);
}

__device__ __forceinline__ void load_tile(const float* __restrict__ z, int t, int N,
                                          uint32_t sb, int buf, int tid) {
    const size_t rowbase = (size_t)t * TILE_M;
    #pragma unroll 4
    for (int i = tid; i < TILE_M * 32; i += TPB) {
        int m = i >> 5, ch = i & 31;
        if (rowbase + m < (size_t)N) {
            uint32_t dst = sb + Z_OFF(buf) + (uint32_t)(m * 512 + (((2 * ch) ^ ((m & 7) * 4)) * 8));
            cp_async16(dst, z + (rowbase + m) * DDIM + ch * 4);
        }
    }
}

__device__ float exact_sm(const char* zb, int rloc, const float* __restrict__ W, int k) {
    const float* wr = W + (size_t)k * DDIM;
    float s = 0.f;
    #pragma unroll 8
    for (int w = 0; w < 64; ++w) {
        float2 p = *(const float2*)(zb + a_off(rloc, w));
        s += p.x * __ldg(wr + 2 * w) + p.y * __ldg(wr + 2 * w + 1);
    }
    return s;
}

__global__ __launch_bounds__(TPB, 1) void vq_hmma_kernel(
    const float* __restrict__ z, const float* __restrict__ W,
    float* __restrict__ out, int N, int ntiles)
{
    extern __shared__ char smem[];
    const uint32_t sb = smem_u32(smem);
    const int tid  = threadIdx.x;
    const int wid  = tid >> 5, lane = tid & 31;
    const int g    = lane >> 2, c = lane & 3;

    float* csh  = (float*)(smem + CSH_OFF);
    int*   sidx = (int*)(smem + SIDX_OFF);

    // ---- stage W split planes + csh (once) ----
    for (int i = tid; i < KCODES * 64; i += TPB) {
        int n = i >> 6, w = i & 63;
        float x0 = __ldg(W + n * DDIM + 2 * w);
        float x1 = __ldg(W + n * DDIM + 2 * w + 1);
        uint32_t hi, lo; split_pair(x0, x1, hi, lo);
        *(uint32_t*)(smem + WP_OFF(0) + w_off(n, w)) = hi;
        *(uint32_t*)(smem + WP_OFF(1) + w_off(n, w)) = lo;
    }
    if (tid < KCODES) {
        const float4* wr = (const float4*)(W + (size_t)tid * DDIM);
        float s = 0.f;
        #pragma unroll
        for (int q = 0; q < DDIM / 4; ++q) {
            float4 v = __ldg(wr + q);
            s += v.x * v.x + v.y * v.y + v.z * v.z + v.w * v.w;
        }
        csh[tid] = 0.5f * s;
    }
    __syncthreads();

    const int nct = gridDim.x;
    int t = blockIdx.x;
    int buf = 0;

    load_tile(z, t, N, sb, 0, tid);
    CP_COMMIT(); CP_WAIT0();
    __syncthreads();

    while (true) {
        const int tn = t + nct;
        const bool hn = tn < ntiles;
        if (hn) { load_tile(z, tn, N, sb, buf ^ 1, tid); CP_COMMIT(); }

        // ---- compute: warp wid owns rows [wid*16, wid*16+16) x 128 codes ----
        float acc[16][4];
        #pragma unroll
        for (int nt = 0; nt < 16; ++nt)
            #pragma unroll
            for (int q = 0; q < 4; ++q) acc[nt][q] = 0.f;

        const char* zb  = smem + Z_OFF(buf);
        const char* wp0 = smem + WP_OFF(0);
        const char* wp1 = smem + WP_OFF(1);

        #pragma unroll 1
        for (int kt = 0; kt < 8; ++kt) {
            uint32_t Ah[4], Al[4];
            {
                int r0 = wid * 16 + g;
                float2 p0 = *(const float2*)(zb + a_off(r0,     8 * kt + c));
                float2 p1 = *(const float2*)(zb + a_off(r0 + 8, 8 * kt + c));
                float2 p2 = *(const float2*)(zb + a_off(r0,     8 * kt + c + 4));
                float2 p3 = *(const float2*)(zb + a_off(r0 + 8, 8 * kt + c + 4));
                split_pair(p0.x, p0.y, Ah[0], Al[0]);
                split_pair(p1.x, p1.y, Ah[1], Al[1]);
                split_pair(p2.x, p2.y, Ah[2], Al[2]);
                split_pair(p3.x, p3.y, Ah[3], Al[3]);
            }
            #pragma unroll
            for (int nt = 0; nt < 16; ++nt) {
                int n = 8 * nt + g;
                uint32_t bh0 = *(const uint32_t*)(wp0 + w_off(n, 8 * kt + c));
                uint32_t bh1 = *(const uint32_t*)(wp0 + w_off(n, 8 * kt + c + 4));
                uint32_t bl0 = *(const uint32_t*)(wp1 + w_off(n, 8 * kt + c));
                uint32_t bl1 = *(const uint32_t*)(wp1 + w_off(n, 8 * kt + c + 4));
                mma_bf16(acc[nt], Ah, bh0, bh1);
                mma_bf16(acc[nt], Ah, bl0, bl1);
                mma_bf16(acc[nt], Al, bh0, bh1);
            }
        }

        // ---- epilogue: top-2 per row, merge across the 4-lane group ----
        #pragma unroll
        for (int rh = 0; rh < 2; ++rh) {
            float v1 = -3.402823466e38f, v2 = -3.402823466e38f;
            int i1 = 0, i2 = 0;
            #pragma unroll
            for (int nt = 0; nt < 16; ++nt) {
                int k0 = nt * 8 + c * 2;
                float s0 = acc[nt][rh * 2]     - csh[k0];
                float s1 = acc[nt][rh * 2 + 1] - csh[k0 + 1];
                if (s0 > v1)      { v2 = v1; i2 = i1; v1 = s0; i1 = k0; }
                else if (s0 > v2) { v2 = s0; i2 = k0; }
                if (s1 > v1)      { v2 = v1; i2 = i1; v1 = s1; i1 = k0 + 1; }
                else if (s1 > v2) { v2 = s1; i2 = k0 + 1; }
            }
            #pragma unroll
            for (int m_ = 1; m_ <= 2; m_ <<= 1) {
                float ov1 = __shfl_xor_sync(0xffffffffu, v1, m_);
                int   oi1 = __shfl_xor_sync(0xffffffffu, i1, m_);
                float ov2 = __shfl_xor_sync(0xffffffffu, v2, m_);
                int   oi2 = __shfl_xor_sync(0xffffffffu, i2, m_);
                if (better(ov1, oi1, v1, i1)) {
                    if (better(v1, i1, ov2, oi2)) { v2 = v1; i2 = i1; }
                    else                          { v2 = ov2; i2 = oi2; }
                    v1 = ov1; i1 = oi1;
                } else if (better(ov1, oi1, v2, i2)) {
                    v2 = ov1; i2 = oi1;
                }
            }
            if (c == 0) {
                int rloc = wid * 16 + rh * 8 + g;
                int rg   = t * TILE_M + rloc;
                int choice = i1;
                if (rg < N && (v1 - v2) < MARGIN) {
                    float e1 = exact_sm(zb, rloc, W, i1) - csh[i1];
                    float e2 = exact_sm(zb, rloc, W, i2) - csh[i2];
                    if (better(e2, i2, e1, i1)) choice = i2;
                }
                sidx[rloc] = choice;
            }
        }
        __syncthreads();

        // ---- gather W[idx] and write both output halves (coalesced) ----
        {
            const int base = t * TILE_M;
            const int rows = min(TILE_M, N - base);
            float4* o1 = (float4*)out;
            float4* o2 = o1 + (size_t)N * (DDIM / 4);
            for (int i = tid; i < rows * (DDIM / 4); i += TPB) {
                int r = i >> 5, dq = i & 31;
                float4 v = __ldg((const float4*)(W + (size_t)sidx[r] * DDIM) + dq);
                size_t off = (size_t)(base + r) * (DDIM / 4) + dq;
                o1[off] = v;
                o2[off] = v;
            }
        }

        if (!hn) break;
        CP_WAIT0();
        __syncthreads();
        t = tn; buf ^= 1;
    }
}

extern "C" void kernel_launch(void* const* d_in, const int* in_sizes, int n_in,
                              void* d_out, int out_size) {
    const float* z = (const float*)d_in[0];
    const float* W = (const float*)d_in[1];
    int N = in_sizes[0] / DDIM;
    int ntiles = (N + TILE_M - 1) / TILE_M;

    int nsm = 148;
    cudaDeviceGetAttribute(&nsm, cudaDevAttrMultiProcessorCount, 0);

    cudaFuncSetAttribute(vq_hmma_kernel, cudaFuncAttributeMaxDynamicSharedMemorySize, SMEM_BYTES);
    int grid = ntiles < nsm ? ntiles : nsm;
    vq_hmma_kernel<<<grid, TPB, SMEM_BYTES>>>(z, W, (float*)d_out, N, ntiles);
}